// round 16
// baseline (speedup 1.0000x reference)
#include <cuda_runtime.h>
#include <cuda_fp16.h>
#include <math.h>
#include <stdint.h>

// ---------------- problem constants ----------------
#define N_MICRO_MAX 500000
#define MICRO_DIM   512
#define N_NODES_C   20000
#define N_EDGES_C   40000
#define NSEG        60000
#define NSEG_PAD    60032          // 938 * 64
#define EPS_SM      1e-8f
#define EPS_LN      1e-5f

#define CHUNK       1024
#define NB_CHUNK    59

// ---------------- device scratch ----------------
__device__ int   g_cc[2 * NSEG];          // [0,NSEG)=counts, [NSEG,2*NSEG)=cursor — single memset
#define G_COUNTS  (g_cc)
#define G_CURSOR  (g_cc + NSEG)
__device__ int   g_offsets[NSEG];
__device__ int   g_rows[N_MICRO_MAX];
__device__ __align__(128) __half g_a_h[(size_t)NSEG_PAD * MICRO_DIM];   // A fp16 (zero-init pad)
__device__ __align__(128) __half g_wt_h[MICRO_DIM * MICRO_DIM];         // W^T [N][K], fp16

// ---------------- helpers ----------------
__device__ __forceinline__ uint32_t smem_u32(const void* p) {
    uint32_t a;
    asm("{ .reg .u64 t; cvta.to.shared.u64 t, %1; cvt.u32.u64 %0, t; }" : "=r"(a) : "l"(p));
    return a;
}

__device__ __forceinline__ int seg_of(int m) {
    if (m >= 0) return m;
    if (m == -100) return -1;
    return N_NODES_C + (-m - 1);
}

__device__ __forceinline__ void ldsm4(uint32_t* r, uint32_t addr) {
    asm volatile("ldmatrix.sync.aligned.m8n8.x4.shared.b16 {%0,%1,%2,%3}, [%4];"
        : "=r"(r[0]), "=r"(r[1]), "=r"(r[2]), "=r"(r[3]) : "r"(addr));
}

__device__ __forceinline__ void mma_fp16(float* d, const uint32_t* a, const uint32_t* b) {
    asm volatile("mma.sync.aligned.m16n8k16.row.col.f32.f16.f16.f32 "
        "{%0,%1,%2,%3},{%4,%5,%6,%7},{%8,%9},{%0,%1,%2,%3};"
        : "+f"(d[0]), "+f"(d[1]), "+f"(d[2]), "+f"(d[3])
        : "r"(a[0]), "r"(a[1]), "r"(a[2]), "r"(a[3]), "r"(b[0]), "r"(b[1]));
}

#define CP_ASYNC16(dst, src) \
    asm volatile("cp.async.cg.shared.global [%0], [%1], 16;" :: "r"(dst), "l"(src))
#define CP_COMMIT() asm volatile("cp.async.commit_group;" ::: "memory")
#define CP_WAITG(n) asm volatile("cp.async.wait_group %0;" :: "n"(n) : "memory")

__device__ __forceinline__ float gelu_exact(float y) {
    return 0.5f * y * (1.f + erff(y * 0.70710678118654752f));
}

// ---------------- 1) count + W transpose/fp16 convert (fused, independent work) ----------------
__global__ void count_wsplit_kernel(const int* __restrict__ m2m, int n,
                                    const float* __restrict__ W) {
    int i = blockIdx.x * blockDim.x + threadIdx.x;
    if (i < n) {
        int s = seg_of(m2m[i]);
        if (s >= 0) atomicAdd(&G_COUNTS[s], 1);
    }
    if (i < MICRO_DIM * MICRO_DIM) {          // 262144 < n
        int k = i >> 9, nn = i & 511;
        g_wt_h[nn * MICRO_DIM + k] = __float2half_rn(W[i]);
    }
}

// ---------------- 2) ONE-kernel exclusive scan ----------------
__global__ void __launch_bounds__(256)
scan_one_kernel() {
    __shared__ int sh[256];
    int b = blockIdx.x, t = threadIdx.x;
    int lim = b * CHUNK;
    int s = 0;
    for (int i = t; i < lim; i += 256) s += G_COUNTS[i];    // coalesced
    sh[t] = s; __syncthreads();
    for (int d = 128; d; d >>= 1) { if (t < d) sh[t] += sh[t + d]; __syncthreads(); }
    int prev = sh[0];                                       // total before this chunk

    if (t < 32) {
        int lane = t;
        int base = b * CHUNK + lane * 32;
        int vals[32];
        int lsum = 0;
        #pragma unroll
        for (int j = 0; j < 32; j++) {
            int i = base + j;
            vals[j] = (i < NSEG) ? G_COUNTS[i] : 0;
            lsum += vals[j];
        }
        int pre = lsum;
        #pragma unroll
        for (int d = 1; d < 32; d <<= 1) {
            int x = __shfl_up_sync(0xffffffffu, pre, d);
            if (lane >= d) pre += x;
        }
        pre -= lsum;
        int carry = prev + pre;
        #pragma unroll
        for (int j = 0; j < 32; j++) {
            int i = base + j;
            if (i < NSEG) g_offsets[i] = carry;
            carry += vals[j];
        }
    }
}

// ---------------- 3) scatter ----------------
__global__ void scatter_kernel(const int* __restrict__ m2m, int n) {
    int i = blockIdx.x * blockDim.x + threadIdx.x;
    if (i < n) {
        int s = seg_of(m2m[i]);
        if (s >= 0) {
            int pos = g_offsets[s] + atomicAdd(&G_CURSOR[s], 1);
            g_rows[pos] = i;
        }
    }
}

// ---------------- 4) warp-per-segment online-softmax aggregation ----------------
__global__ void __launch_bounds__(256, 3)
agg_warp_kernel(const float* __restrict__ feat,
                const float* __restrict__ attn_w,
                const float* __restrict__ attn_bp) {
    __shared__ float s_aw[MICRO_DIM];
    for (int j = threadIdx.x; j < MICRO_DIM; j += 256) s_aw[j] = attn_w[j];
    __syncthreads();

    int wid  = threadIdx.x >> 5;
    int lane = threadIdx.x & 31;
    int seg  = blockIdx.x * 8 + wid;
    if (seg >= NSEG) return;

    int cnt = G_COUNTS[seg];
    int off = g_offsets[seg];
    size_t outbase = (size_t)seg * MICRO_DIM;

    if (cnt == 0) {
        uint2 z = make_uint2(0u, 0u);
        #pragma unroll
        for (int k = 0; k < 4; k++) {
            int fi = lane + 32 * k;
            *(uint2*)(g_a_h + outbase + fi * 4) = z;
        }
        return;
    }

    float ab = attn_bp[0];
    float m = -INFINITY, s = 0.f;
    float acc[16];
    #pragma unroll
    for (int i = 0; i < 16; i++) acc[i] = 0.f;

    for (int r = 0; r < cnt; r++) {
        int row = g_rows[off + r];
        const float4* fp = (const float4*)(feat + (size_t)row * MICRO_DIM);
        float4 v[4];
        #pragma unroll
        for (int k = 0; k < 4; k++) v[k] = fp[lane + 32 * k];

        float dot = 0.f;
        #pragma unroll
        for (int k = 0; k < 4; k++) {
            float4 w = ((const float4*)s_aw)[lane + 32 * k];
            dot += v[k].x * w.x + v[k].y * w.y + v[k].z * w.z + v[k].w * w.w;
        }
        #pragma unroll
        for (int d = 16; d; d >>= 1) dot += __shfl_xor_sync(0xffffffffu, dot, d);
        float l = dot + ab;

        float mn = fmaxf(m, l);
        float sc = __expf(m - mn);
        float e  = __expf(l - mn);
        #pragma unroll
        for (int k = 0; k < 4; k++) {
            acc[4*k+0] = acc[4*k+0] * sc + e * v[k].x;
            acc[4*k+1] = acc[4*k+1] * sc + e * v[k].y;
            acc[4*k+2] = acc[4*k+2] * sc + e * v[k].z;
            acc[4*k+3] = acc[4*k+3] * sc + e * v[k].w;
        }
        s = s * sc + e;
        m = mn;
    }

    float inv = 1.f / (s + EPS_SM);
    #pragma unroll
    for (int k = 0; k < 4; k++) {
        int fi = lane + 32 * k;
        __half2 p01 = __floats2half2_rn(acc[4*k+0] * inv, acc[4*k+1] * inv);
        __half2 p23 = __floats2half2_rn(acc[4*k+2] * inv, acc[4*k+3] * inv);
        *(uint2*)(g_a_h + outbase + fi * 4) =
            make_uint2(*(uint32_t*)&p01, *(uint32_t*)&p23);
    }
}

// ---------------- 5) fused fp16 GEMM + bias + LayerNorm + GELU ----------------
// CTA tile 64x512 (full output rows -> LN in epilogue). 512 threads = 4 m x 4 n warps,
// warp tile 16x128. B (0.5 MB fp16) is L2-resident across the 938 CTAs.
#define GT_M      64
#define GKC       32
#define GNCHUNK   16
#define ROWB      80
#define A_MAT     (GT_M * ROWB)        // 5120
#define B_MAT     (512 * ROWB)         // 40960
#define A_OFF     0
#define B_OFF     A_MAT
#define STAGE_SZ  (A_MAT + B_MAT)      // 46080
#define NSTAGE    3
#define STAT_OFF  (NSTAGE * STAGE_SZ)  // 138240: 4 warp_n x 64 rows x 2 floats
#define SMEM_GF   (NSTAGE * STAGE_SZ + 2048)   // 140288

__global__ void __launch_bounds__(512, 1)
gemm_fused_kernel(const float* __restrict__ pb,
                  const float* __restrict__ lng,
                  const float* __restrict__ lnb,
                  float* __restrict__ out, int M) {
    extern __shared__ char smem[];
    uint32_t sbase = smem_u32(smem);

    int tid  = threadIdx.x;
    int lane = tid & 31, wid = tid >> 5;
    int warp_m = wid & 3;          // 16-row slice
    int warp_n = wid >> 2;         // 128-col slice
    int rowBase = blockIdx.x * GT_M;

    float acc[16][4];
    #pragma unroll
    for (int j = 0; j < 16; j++)
        #pragma unroll
        for (int q = 0; q < 4; q++) acc[j][q] = 0.f;

    // cp.async per chunk: A = 256 16B copies (threads 0-255), B = 2048 (4/thread)
    #define GF_ISSUE(c) do {                                                          \
        uint32_t sb_ = sbase + ((c) % NSTAGE) * STAGE_SZ;                             \
        int k0_ = (c) * GKC;                                                          \
        if (tid < 256) {                                                              \
            int r_ = tid >> 2, q_ = tid & 3;                                          \
            const __half* s_ = g_a_h + (size_t)(rowBase + r_) * MICRO_DIM             \
                               + q_ * 8 + k0_;                                        \
            CP_ASYNC16(sb_ + A_OFF + r_ * ROWB + q_ * 16, s_);                        \
        }                                                                             \
        _Pragma("unroll")                                                             \
        for (int i_ = 0; i_ < 4; i_++) {                                              \
            int f_ = tid + i_ * 512;                                                  \
            int r_ = f_ >> 2, q_ = f_ & 3;                                            \
            const __half* s_ = g_wt_h + (size_t)r_ * MICRO_DIM + q_ * 8 + k0_;        \
            CP_ASYNC16(sb_ + B_OFF + r_ * ROWB + q_ * 16, s_);                        \
        }                                                                             \
        CP_COMMIT();                                                                  \
    } while (0)

    int a_r = (lane & 7) + ((lane >> 3) & 1) * 8;
    int a_o = (lane >> 4) * 16;
    int b_r = (lane & 7) + ((lane >> 4) & 1) * 8;
    int b_o = ((lane >> 3) & 1) * 16;

    GF_ISSUE(0);
    GF_ISSUE(1);

    for (int c = 0; c < GNCHUNK; c++) {
        CP_WAITG(1);
        __syncthreads();

        uint32_t stage = sbase + (c % NSTAGE) * STAGE_SZ;
        #pragma unroll
        for (int s = 0; s < 2; s++) {
            uint32_t ah[4];
            uint32_t aoff = (uint32_t)((warp_m * 16 + a_r) * ROWB + s * 32 + a_o);
            ldsm4(ah, stage + A_OFF + aoff);
            #pragma unroll
            for (int p = 0; p < 8; p++) {
                uint32_t bh[4];
                uint32_t boff = (uint32_t)((warp_n * 128 + p * 16 + b_r) * ROWB + s * 32 + b_o);
                ldsm4(bh, stage + B_OFF + boff);
                mma_fp16(acc[2 * p],     ah, &bh[0]);
                mma_fp16(acc[2 * p + 1], ah, &bh[2]);
            }
        }
        if (c + 2 < GNCHUNK)       GF_ISSUE(c + 2);
        else if (c + 2 == GNCHUNK) CP_COMMIT();   // empty group: makes final wait exact
    }

    // ---- epilogue: bias + LN stats (quad shuffle + smem across warp_n) + GELU ----
    int r0 = warp_m * 16 + (lane >> 2);      // tile-local rows
    int r1 = r0 + 8;
    float s0 = 0.f, q0 = 0.f, s1 = 0.f, q1 = 0.f;
    #pragma unroll
    for (int nt = 0; nt < 16; nt++) {
        int col = warp_n * 128 + nt * 8 + (lane & 3) * 2;
        float2 b2 = *(const float2*)(pb + col);
        acc[nt][0] += b2.x; acc[nt][1] += b2.y;
        acc[nt][2] += b2.x; acc[nt][3] += b2.y;
        s0 += acc[nt][0] + acc[nt][1];
        q0 += acc[nt][0] * acc[nt][0] + acc[nt][1] * acc[nt][1];
        s1 += acc[nt][2] + acc[nt][3];
        q1 += acc[nt][2] * acc[nt][2] + acc[nt][3] * acc[nt][3];
    }
    #pragma unroll
    for (int d = 1; d < 4; d <<= 1) {
        s0 += __shfl_xor_sync(0xffffffffu, s0, d);
        q0 += __shfl_xor_sync(0xffffffffu, q0, d);
        s1 += __shfl_xor_sync(0xffffffffu, s1, d);
        q1 += __shfl_xor_sync(0xffffffffu, q1, d);
    }
    float* st = (float*)(smem + STAT_OFF);
    if ((lane & 3) == 0) {
        st[(warp_n * 64 + r0) * 2 + 0] = s0;
        st[(warp_n * 64 + r0) * 2 + 1] = q0;
        st[(warp_n * 64 + r1) * 2 + 0] = s1;
        st[(warp_n * 64 + r1) * 2 + 1] = q1;
    }
    __syncthreads();

    float sS0 = 0.f, sQ0 = 0.f, sS1 = 0.f, sQ1 = 0.f;
    #pragma unroll
    for (int wn = 0; wn < 4; wn++) {
        sS0 += st[(wn * 64 + r0) * 2 + 0];
        sQ0 += st[(wn * 64 + r0) * 2 + 1];
        sS1 += st[(wn * 64 + r1) * 2 + 0];
        sQ1 += st[(wn * 64 + r1) * 2 + 1];
    }
    float mu0 = sS0 * (1.f / 512.f);
    float mu1 = sS1 * (1.f / 512.f);
    float rs0 = rsqrtf(sQ0 * (1.f / 512.f) - mu0 * mu0 + EPS_LN);
    float rs1 = rsqrtf(sQ1 * (1.f / 512.f) - mu1 * mu1 + EPS_LN);

    int gr0 = rowBase + r0, gr1 = rowBase + r1;
    bool ok0 = gr0 < M, ok1 = gr1 < M;
    float* o0 = out + (size_t)gr0 * MICRO_DIM;
    float* o1 = out + (size_t)gr1 * MICRO_DIM;
    #pragma unroll
    for (int nt = 0; nt < 16; nt++) {
        int col = warp_n * 128 + nt * 8 + (lane & 3) * 2;
        float2 gg = *(const float2*)(lng + col);
        float2 bb = *(const float2*)(lnb + col);
        if (ok0) {
            float y0 = (acc[nt][0] - mu0) * rs0 * gg.x + bb.x;
            float y1 = (acc[nt][1] - mu0) * rs0 * gg.y + bb.y;
            *(float2*)(o0 + col) = make_float2(gelu_exact(y0), gelu_exact(y1));
        }
        if (ok1) {
            float y2 = (acc[nt][2] - mu1) * rs1 * gg.x + bb.x;
            float y3 = (acc[nt][3] - mu1) * rs1 * gg.y + bb.y;
            *(float2*)(o1 + col) = make_float2(gelu_exact(y2), gelu_exact(y3));
        }
    }
    #undef GF_ISSUE
}

// ---------------- launch ----------------
extern "C" void kernel_launch(void* const* d_in, const int* in_sizes, int n_in,
                              void* d_out, int out_size) {
    const float* feat   = (const float*)d_in[0];
    const float* attn_w = (const float*)d_in[1];
    const float* attn_b = (const float*)d_in[2];
    const float* proj_w = (const float*)d_in[3];
    const float* proj_b = (const float*)d_in[4];
    const float* ln_g   = (const float*)d_in[5];
    const float* ln_b   = (const float*)d_in[6];
    const int*   m2m    = (const int*)d_in[7];
    int n = in_sizes[7];
    float* out = (float*)d_out;

    static int* cc_ptr = nullptr;
    if (!cc_ptr) {
        cudaGetSymbolAddress((void**)&cc_ptr, g_cc);
        cudaFuncSetAttribute(gemm_fused_kernel,
                             cudaFuncAttributeMaxDynamicSharedMemorySize, SMEM_GF);
    }

    cudaMemsetAsync(cc_ptr, 0, 2 * NSEG * sizeof(int), 0);     // counts + cursor in one node

    count_wsplit_kernel<<<(n + 255) / 256, 256>>>(m2m, n, proj_w);   // kernel 1
    scan_one_kernel<<<NB_CHUNK, 256>>>();                            // kernel 2
    scatter_kernel<<<(n + 255) / 256, 256>>>(m2m, n);                // kernel 3
    agg_warp_kernel<<<(NSEG + 7) / 8, 256>>>(feat, attn_w, attn_b);  // kernel 4 (profiled)

    gemm_fused_kernel<<<NSEG_PAD / GT_M, 512, SMEM_GF>>>(proj_b, ln_g, ln_b, out, NSEG);  // kernel 5
}

// round 17
// speedup vs baseline: 1.1465x; 1.1465x over previous
#include <cuda_runtime.h>
#include <cuda_fp16.h>
#include <math.h>
#include <stdint.h>

// ---------------- problem constants ----------------
#define N_MICRO_MAX 500000
#define MICRO_DIM   512
#define N_NODES_C   20000
#define N_EDGES_C   40000
#define NSEG        60000
#define NSEG_PAD    60032          // 469 * 128
#define EPS_SM      1e-8f
#define EPS_LN      1e-5f

#define CHUNK       1024
#define NB_CHUNK    59

// ---------------- device scratch ----------------
__device__ int   g_cc[2 * NSEG];          // [0,NSEG)=counts, [NSEG,2*NSEG)=cursor — single memset
#define G_COUNTS  (g_cc)
#define G_CURSOR  (g_cc + NSEG)
__device__ int   g_offsets[NSEG];
__device__ int   g_rows[N_MICRO_MAX];
__device__ __align__(128) __half g_a_h[(size_t)NSEG_PAD * MICRO_DIM];   // A fp16 (zero-init pad)
__device__ __align__(128) __half g_wt_h[MICRO_DIM * MICRO_DIM];         // W^T [N][K], fp16

// ---------------- helpers ----------------
__device__ __forceinline__ uint32_t smem_u32(const void* p) {
    uint32_t a;
    asm("{ .reg .u64 t; cvta.to.shared.u64 t, %1; cvt.u32.u64 %0, t; }" : "=r"(a) : "l"(p));
    return a;
}

__device__ __forceinline__ int seg_of(int m) {
    if (m >= 0) return m;
    if (m == -100) return -1;
    return N_NODES_C + (-m - 1);
}

__device__ __forceinline__ void ldsm4(uint32_t* r, uint32_t addr) {
    asm volatile("ldmatrix.sync.aligned.m8n8.x4.shared.b16 {%0,%1,%2,%3}, [%4];"
        : "=r"(r[0]), "=r"(r[1]), "=r"(r[2]), "=r"(r[3]) : "r"(addr));
}

__device__ __forceinline__ void mma_fp16(float* d, const uint32_t* a, const uint32_t* b) {
    asm volatile("mma.sync.aligned.m16n8k16.row.col.f32.f16.f16.f32 "
        "{%0,%1,%2,%3},{%4,%5,%6,%7},{%8,%9},{%0,%1,%2,%3};"
        : "+f"(d[0]), "+f"(d[1]), "+f"(d[2]), "+f"(d[3])
        : "r"(a[0]), "r"(a[1]), "r"(a[2]), "r"(a[3]), "r"(b[0]), "r"(b[1]));
}

#define CP_ASYNC16(dst, src) \
    asm volatile("cp.async.cg.shared.global [%0], [%1], 16;" :: "r"(dst), "l"(src))
#define CP_COMMIT() asm volatile("cp.async.commit_group;" ::: "memory")
#define CP_WAITG(n) asm volatile("cp.async.wait_group %0;" :: "n"(n) : "memory")

__device__ __forceinline__ float gelu_exact(float y) {
    return 0.5f * y * (1.f + erff(y * 0.70710678118654752f));
}

// ---------------- 1) count + W transpose/fp16 convert (fused, independent work) ----------------
__global__ void count_wsplit_kernel(const int* __restrict__ m2m, int n,
                                    const float* __restrict__ W) {
    int i = blockIdx.x * blockDim.x + threadIdx.x;
    if (i < n) {
        int s = seg_of(m2m[i]);
        if (s >= 0) atomicAdd(&G_COUNTS[s], 1);
    }
    if (i < MICRO_DIM * MICRO_DIM) {          // 262144 < n
        int k = i >> 9, nn = i & 511;
        g_wt_h[nn * MICRO_DIM + k] = __float2half_rn(W[i]);
    }
}

// ---------------- 2) ONE-kernel exclusive scan ----------------
__global__ void __launch_bounds__(256)
scan_one_kernel() {
    __shared__ int sh[256];
    int b = blockIdx.x, t = threadIdx.x;
    int lim = b * CHUNK;
    int s = 0;
    for (int i = t; i < lim; i += 256) s += G_COUNTS[i];    // coalesced
    sh[t] = s; __syncthreads();
    for (int d = 128; d; d >>= 1) { if (t < d) sh[t] += sh[t + d]; __syncthreads(); }
    int prev = sh[0];                                       // total before this chunk

    if (t < 32) {
        int lane = t;
        int base = b * CHUNK + lane * 32;
        int vals[32];
        int lsum = 0;
        #pragma unroll
        for (int j = 0; j < 32; j++) {
            int i = base + j;
            vals[j] = (i < NSEG) ? G_COUNTS[i] : 0;
            lsum += vals[j];
        }
        int pre = lsum;
        #pragma unroll
        for (int d = 1; d < 32; d <<= 1) {
            int x = __shfl_up_sync(0xffffffffu, pre, d);
            if (lane >= d) pre += x;
        }
        pre -= lsum;
        int carry = prev + pre;
        #pragma unroll
        for (int j = 0; j < 32; j++) {
            int i = base + j;
            if (i < NSEG) g_offsets[i] = carry;
            carry += vals[j];
        }
    }
}

// ---------------- 3) scatter ----------------
__global__ void scatter_kernel(const int* __restrict__ m2m, int n) {
    int i = blockIdx.x * blockDim.x + threadIdx.x;
    if (i < n) {
        int s = seg_of(m2m[i]);
        if (s >= 0) {
            int pos = g_offsets[s] + atomicAdd(&G_CURSOR[s], 1);
            g_rows[pos] = i;
        }
    }
}

// ---------------- 4) warp-per-segment online-softmax aggregation ----------------
// Two-pass per row: pass 1 computes the logit (row regs die), pass 2 reloads the
// row (L1 hit — same warp just touched it) and accumulates. Live regs ~48 -> 4 CTAs/SM.
__global__ void __launch_bounds__(256, 4)
agg_warp_kernel(const float* __restrict__ feat,
                const float* __restrict__ attn_w,
                const float* __restrict__ attn_bp) {
    __shared__ float s_aw[MICRO_DIM];
    for (int j = threadIdx.x; j < MICRO_DIM; j += 256) s_aw[j] = attn_w[j];
    __syncthreads();

    int wid  = threadIdx.x >> 5;
    int lane = threadIdx.x & 31;
    int seg  = blockIdx.x * 8 + wid;
    if (seg >= NSEG) return;

    int cnt = G_COUNTS[seg];
    int off = g_offsets[seg];
    size_t outbase = (size_t)seg * MICRO_DIM;

    if (cnt == 0) {
        uint2 z = make_uint2(0u, 0u);
        #pragma unroll
        for (int k = 0; k < 4; k++) {
            int fi = lane + 32 * k;
            *(uint2*)(g_a_h + outbase + fi * 4) = z;
        }
        return;
    }

    float ab = attn_bp[0];
    float m = -INFINITY, s = 0.f;
    float acc[16];
    #pragma unroll
    for (int i = 0; i < 16; i++) acc[i] = 0.f;

    for (int r = 0; r < cnt; r++) {
        int row = g_rows[off + r];
        const float4* fp = (const float4*)(feat + (size_t)row * MICRO_DIM);

        // pass 1: logit (row registers die immediately)
        float dot = 0.f;
        #pragma unroll
        for (int k = 0; k < 4; k++) {
            float4 v = fp[lane + 32 * k];
            float4 w = ((const float4*)s_aw)[lane + 32 * k];
            dot += v.x * w.x + v.y * w.y + v.z * w.z + v.w * w.w;
        }
        #pragma unroll
        for (int d = 16; d; d >>= 1) dot += __shfl_xor_sync(0xffffffffu, dot, d);
        float l = dot + ab;

        float mn = fmaxf(m, l);
        float sc = __expf(m - mn);
        float e  = __expf(l - mn);

        // pass 2: accumulate (reload hits L1)
        #pragma unroll
        for (int k = 0; k < 4; k++) {
            float4 v = fp[lane + 32 * k];
            acc[4*k+0] = acc[4*k+0] * sc + e * v.x;
            acc[4*k+1] = acc[4*k+1] * sc + e * v.y;
            acc[4*k+2] = acc[4*k+2] * sc + e * v.z;
            acc[4*k+3] = acc[4*k+3] * sc + e * v.w;
        }
        s = s * sc + e;
        m = mn;
    }

    float inv = 1.f / (s + EPS_SM);
    #pragma unroll
    for (int k = 0; k < 4; k++) {
        int fi = lane + 32 * k;
        __half2 p01 = __floats2half2_rn(acc[4*k+0] * inv, acc[4*k+1] * inv);
        __half2 p23 = __floats2half2_rn(acc[4*k+2] * inv, acc[4*k+3] * inv);
        *(uint2*)(g_a_h + outbase + fi * 4) =
            make_uint2(*(uint32_t*)&p01, *(uint32_t*)&p23);
    }
}

// ---------------- 5) mma.sync fp16 GEMM (single-term), 128x256 tile, 3-stage cp.async ----------------
#define GTILE_M   128
#define GTILE_N   256
#define GKC       32
#define GNCHUNK   16
#define ROWB      80
#define A_MAT     (128 * ROWB)       // 10240
#define B_MAT     (256 * ROWB)       // 20480
#define A_OFF     0
#define B_OFF     A_MAT
#define STAGE_SZ  (A_MAT + B_MAT)    // 30720
#define NSTAGE    3
#define SMEM_GEMM (NSTAGE * STAGE_SZ)   // 92160

__global__ void __launch_bounds__(512, 1)
gemm_mma_kernel(float* __restrict__ out, int M) {
    extern __shared__ char smem[];
    uint32_t sbase = smem_u32(smem);

    int tid  = threadIdx.x;
    int lane = tid & 31, wid = tid >> 5;
    int warp_m = wid & 3;          // 32-row slice
    int warp_n = wid >> 2;         // 64-col slice (0..3)
    int rowBase = blockIdx.y * GTILE_M;
    int colBase = blockIdx.x * GTILE_N;

    float acc[2][8][4];
    #pragma unroll
    for (int i = 0; i < 2; i++)
        #pragma unroll
        for (int j = 0; j < 8; j++)
            #pragma unroll
            for (int q = 0; q < 4; q++) acc[i][j][q] = 0.f;

    // cp.async per chunk: A = 512 16B copies (1/thread), B = 1024 (2/thread)
    #define G_ISSUE(c) do {                                                           \
        uint32_t sb_ = sbase + ((c) % NSTAGE) * STAGE_SZ;                             \
        int k0_ = (c) * GKC;                                                          \
        {                                                                             \
            int r_ = tid >> 2, q_ = tid & 3;                                          \
            const __half* s_ = g_a_h + (size_t)(rowBase + r_) * MICRO_DIM             \
                               + q_ * 8 + k0_;                                        \
            CP_ASYNC16(sb_ + A_OFF + r_ * ROWB + q_ * 16, s_);                        \
        }                                                                             \
        _Pragma("unroll")                                                             \
        for (int i_ = 0; i_ < 2; i_++) {                                              \
            int f_ = tid + i_ * 512;                                                  \
            int r_ = f_ >> 2, q_ = f_ & 3;                                            \
            const __half* s_ = g_wt_h + (size_t)(colBase + r_) * MICRO_DIM            \
                               + q_ * 8 + k0_;                                        \
            CP_ASYNC16(sb_ + B_OFF + r_ * ROWB + q_ * 16, s_);                        \
        }                                                                             \
        CP_COMMIT();                                                                  \
    } while (0)

    int a_r = (lane & 7) + ((lane >> 3) & 1) * 8;
    int a_o = (lane >> 4) * 16;
    int b_r = (lane & 7) + ((lane >> 4) & 1) * 8;
    int b_o = ((lane >> 3) & 1) * 16;

    G_ISSUE(0);
    G_ISSUE(1);

    for (int c = 0; c < GNCHUNK; c++) {
        CP_WAITG(1);            // constant-immediate wait keeps the pipeline folded
        __syncthreads();

        uint32_t stage = sbase + (c % NSTAGE) * STAGE_SZ;
        #pragma unroll
        for (int s = 0; s < 2; s++) {
            uint32_t ah[2][4];
            #pragma unroll
            for (int mm = 0; mm < 2; mm++) {
                uint32_t off = (uint32_t)((warp_m * 32 + mm * 16 + a_r) * ROWB + s * 32 + a_o);
                ldsm4(ah[mm], stage + A_OFF + off);
            }
            #pragma unroll
            for (int p = 0; p < 4; p++) {
                uint32_t bh[4];
                uint32_t off = (uint32_t)((warp_n * 64 + p * 16 + b_r) * ROWB + s * 32 + b_o);
                ldsm4(bh, stage + B_OFF + off);
                #pragma unroll
                for (int mm = 0; mm < 2; mm++) {
                    #pragma unroll
                    for (int h = 0; h < 2; h++) {
                        mma_fp16(acc[mm][2 * p + h], ah[mm], &bh[h * 2]);
                    }
                }
            }
        }
        if (c + 2 < GNCHUNK)       G_ISSUE(c + 2);
        else if (c + 2 == GNCHUNK) CP_COMMIT();   // empty group: makes final wait exact
    }

    #pragma unroll
    for (int mm = 0; mm < 2; mm++) {
        int row0 = rowBase + warp_m * 32 + mm * 16 + (lane >> 2);
        #pragma unroll
        for (int nt = 0; nt < 8; nt++) {
            int col = colBase + warp_n * 64 + nt * 8 + (lane & 3) * 2;
            if (row0 < M)
                *(float2*)(out + (size_t)row0 * MICRO_DIM + col) =
                    make_float2(acc[mm][nt][0], acc[mm][nt][1]);
            if (row0 + 8 < M)
                *(float2*)(out + (size_t)(row0 + 8) * MICRO_DIM + col) =
                    make_float2(acc[mm][nt][2], acc[mm][nt][3]);
        }
    }
    #undef G_ISSUE
}

// ---------------- 6) bias + LayerNorm + exact GELU ----------------
__global__ void __launch_bounds__(256)
ln_gelu_kernel(const float* __restrict__ pb,
               const float* __restrict__ lng,
               const float* __restrict__ lnb,
               float* __restrict__ out, int M) {
    int row  = blockIdx.x * 8 + (threadIdx.x >> 5);
    int lane = threadIdx.x & 31;
    if (row >= M) return;

    float4* p = (float4*)(out + (size_t)row * MICRO_DIM);
    const float4* pb4 = (const float4*)pb;
    float x[16];
    float sum = 0.f;
    #pragma unroll
    for (int k = 0; k < 4; k++) {
        float4 h = p[lane + 32 * k];
        float4 b = pb4[lane + 32 * k];
        x[4*k+0] = h.x + b.x; x[4*k+1] = h.y + b.y;
        x[4*k+2] = h.z + b.z; x[4*k+3] = h.w + b.w;
        sum += x[4*k] + x[4*k+1] + x[4*k+2] + x[4*k+3];
    }
    #pragma unroll
    for (int d = 16; d; d >>= 1) sum += __shfl_xor_sync(0xffffffffu, sum, d);
    float mu = sum * (1.f / 512.f);

    float v = 0.f;
    #pragma unroll
    for (int i = 0; i < 16; i++) { float dlt = x[i] - mu; v += dlt * dlt; }
    #pragma unroll
    for (int d = 16; d; d >>= 1) v += __shfl_xor_sync(0xffffffffu, v, d);
    v *= (1.f / 512.f);
    float rs = rsqrtf(v + EPS_LN);

    const float4* g4 = (const float4*)lng;
    const float4* b4 = (const float4*)lnb;
    #pragma unroll
    for (int k = 0; k < 4; k++) {
        float4 gg = g4[lane + 32 * k];
        float4 bb = b4[lane + 32 * k];
        float4 o;
        float y;
        y = (x[4*k+0] - mu) * rs * gg.x + bb.x; o.x = gelu_exact(y);
        y = (x[4*k+1] - mu) * rs * gg.y + bb.y; o.y = gelu_exact(y);
        y = (x[4*k+2] - mu) * rs * gg.z + bb.z; o.z = gelu_exact(y);
        y = (x[4*k+3] - mu) * rs * gg.w + bb.w; o.w = gelu_exact(y);
        p[lane + 32 * k] = o;
    }
}

// ---------------- launch ----------------
extern "C" void kernel_launch(void* const* d_in, const int* in_sizes, int n_in,
                              void* d_out, int out_size) {
    const float* feat   = (const float*)d_in[0];
    const float* attn_w = (const float*)d_in[1];
    const float* attn_b = (const float*)d_in[2];
    const float* proj_w = (const float*)d_in[3];
    const float* proj_b = (const float*)d_in[4];
    const float* ln_g   = (const float*)d_in[5];
    const float* ln_b   = (const float*)d_in[6];
    const int*   m2m    = (const int*)d_in[7];
    int n = in_sizes[7];
    float* out = (float*)d_out;

    static int* cc_ptr = nullptr;
    if (!cc_ptr) {
        cudaGetSymbolAddress((void**)&cc_ptr, g_cc);
        cudaFuncSetAttribute(gemm_mma_kernel,
                             cudaFuncAttributeMaxDynamicSharedMemorySize, SMEM_GEMM);
    }

    cudaMemsetAsync(cc_ptr, 0, 2 * NSEG * sizeof(int), 0);     // counts + cursor in one node

    count_wsplit_kernel<<<(n + 255) / 256, 256>>>(m2m, n, proj_w);   // kernel 1
    scan_one_kernel<<<NB_CHUNK, 256>>>();                            // kernel 2
    scatter_kernel<<<(n + 255) / 256, 256>>>(m2m, n);                // kernel 3
    agg_warp_kernel<<<(NSEG + 7) / 8, 256>>>(feat, attn_w, attn_b);  // kernel 4 (profiled)

    dim3 ggrid(MICRO_DIM / GTILE_N, NSEG_PAD / GTILE_M);             // (2, 469)
    gemm_mma_kernel<<<ggrid, 512, SMEM_GEMM>>>(out, NSEG);           // kernel 5

    ln_gelu_kernel<<<(NSEG + 7) / 8, 256>>>(proj_b, ln_g, ln_b, out, NSEG);  // kernel 6
}